// round 12
// baseline (speedup 1.0000x reference)
#include <cuda_runtime.h>
#include <cuda_fp16.h>
#include <math.h>

#define F1 128
#define MAXN 100096
#define CAP  128           // bucket capacity per node

// ---------------- static device scratch ----------------
__device__ __half g_h1h[MAXN * F1];      // fp16 projected features (gather table)
__device__ __half g_W1f[128 * 128];      // W1 fp16, pre-swizzled into mma B-fragment order
__device__ float  g_s1s[MAXN];
__device__ float  g_s1d[MAXN];
__device__ float4 g_n2[MAXN];            // packed layer-2 node data {h0, h1, s2s, s2d}
__device__ int    g_cnt[MAXN];
__device__ int    g_csr_src[MAXN * CAP];

__device__ __forceinline__ float lrelu(float e) { return fmaxf(e, 0.2f * e); }

// ---------------- kernels ----------------
// Merged init: self-loop plant + cnt=1, AND W1 fragment pre-swizzle.
__global__ void k_init(const float* __restrict__ W1, int N) {
    int i = blockIdx.x * blockDim.x + threadIdx.x;
    int stride = gridDim.x * blockDim.x;
    for (int idx = i; idx < N; idx += stride) {
        g_cnt[idx] = 1;
        g_csr_src[idx << 7] = idx;
    }
    if (i < 4096) {
        int lane = i & 31, nt = (i >> 5) & 15, ks = i >> 9;
        int kb = ks * 16 + (lane & 3) * 2;
        int n  = nt * 8 + (lane >> 2);
        __half h0 = __float2half_rn(W1[(kb + 0) * 128 + n]);
        __half h1 = __float2half_rn(W1[(kb + 1) * 128 + n]);
        __half h2 = __float2half_rn(W1[(kb + 8) * 128 + n]);
        __half h3 = __float2half_rn(W1[(kb + 9) * 128 + n]);
        __half2* out = (__half2*)g_W1f;
        out[i * 2 + 0] = __halves2half2(h0, h1);
        out[i * 2 + 1] = __halves2half2(h2, h3);
    }
}

// Tensor-core GEMM: 128 nodes x 128 out per block (256 thr, 8 warps).
#define XROW 136   // padded smem row stride in halves
#define GEMM1_SMEM (128 * XROW * 2 + 128 * 128 * 2)
__global__ void k_gemm1(const float* __restrict__ x,
                        const float* __restrict__ a_src, const float* __restrict__ a_dst,
                        int N) {
    extern __shared__ __align__(16) char dynsmem[];
    __half* sxh = (__half*)dynsmem;                    // 128*XROW halves
    __half* sW1 = (__half*)(dynsmem + 128 * XROW * 2); // 128*128 halves

    int tid = threadIdx.x;
    int nbase = blockIdx.x * 128;

    const float4* x4 = (const float4*)x;
#pragma unroll
    for (int i = 0; i < 16; i++) {
        int f = tid + 256 * i;
        int row = f >> 5, kc = (f & 31) * 4;
        int n = nbase + row;
        float4 v = (n < N) ? x4[n * 32 + (f & 31)] : make_float4(0.f, 0.f, 0.f, 0.f);
        *(__half2*)&sxh[row * XROW + kc]     = __floats2half2_rn(v.x, v.y);
        *(__half2*)&sxh[row * XROW + kc + 2] = __floats2half2_rn(v.z, v.w);
    }
    {
        const uint2* src = (const uint2*)g_W1f;
        uint2* dst = (uint2*)sW1;
#pragma unroll
        for (int i = 0; i < 16; i++) dst[tid + 256 * i] = src[tid + 256 * i];
    }
    __syncthreads();

    int w = tid >> 5, lane = tid & 31;
    int mt16 = w * 16;
    int r = lane >> 2, cq = (lane & 3) * 2;

    float c[16][4];
#pragma unroll
    for (int nt = 0; nt < 16; nt++)
#pragma unroll
        for (int j = 0; j < 4; j++) c[nt][j] = 0.f;

    const uint2* W1f2 = (const uint2*)sW1;
#pragma unroll
    for (int ks = 0; ks < 8; ks++) {
        int k0 = ks * 16;
        unsigned a0 = *(const unsigned*)&sxh[(mt16 + r) * XROW + k0 + cq];
        unsigned a1 = *(const unsigned*)&sxh[(mt16 + r + 8) * XROW + k0 + cq];
        unsigned a2 = *(const unsigned*)&sxh[(mt16 + r) * XROW + k0 + cq + 8];
        unsigned a3 = *(const unsigned*)&sxh[(mt16 + r + 8) * XROW + k0 + cq + 8];
#pragma unroll
        for (int nt = 0; nt < 16; nt++) {
            uint2 b = W1f2[(ks * 16 + nt) * 32 + lane];
            asm volatile(
                "mma.sync.aligned.m16n8k16.row.col.f32.f16.f16.f32 "
                "{%0,%1,%2,%3}, {%4,%5,%6,%7}, {%8,%9}, {%0,%1,%2,%3};"
                : "+f"(c[nt][0]), "+f"(c[nt][1]), "+f"(c[nt][2]), "+f"(c[nt][3])
                : "r"(a0), "r"(a1), "r"(a2), "r"(a3), "r"(b.x), "r"(b.y));
        }
    }

    int node0 = nbase + mt16 + r;
    int node1 = node0 + 8;
    float p0 = 0.f, q0 = 0.f, p1 = 0.f, q1 = 0.f;
    __half2* h1v = (__half2*)g_h1h;
#pragma unroll
    for (int nt = 0; nt < 16; nt++) {
        int col = nt * 8 + cq;
        float as0 = a_src[col], as1 = a_src[col + 1];
        float ad0 = a_dst[col], ad1 = a_dst[col + 1];
        p0 += c[nt][0] * as0 + c[nt][1] * as1;
        q0 += c[nt][0] * ad0 + c[nt][1] * ad1;
        p1 += c[nt][2] * as0 + c[nt][3] * as1;
        q1 += c[nt][2] * ad0 + c[nt][3] * ad1;
        if (node0 < N) h1v[node0 * 64 + (col >> 1)] = __floats2half2_rn(c[nt][0], c[nt][1]);
        if (node1 < N) h1v[node1 * 64 + (col >> 1)] = __floats2half2_rn(c[nt][2], c[nt][3]);
    }
#pragma unroll
    for (int o = 1; o <= 2; o <<= 1) {
        p0 += __shfl_xor_sync(0xffffffffu, p0, o);
        q0 += __shfl_xor_sync(0xffffffffu, q0, o);
        p1 += __shfl_xor_sync(0xffffffffu, p1, o);
        q1 += __shfl_xor_sync(0xffffffffu, q1, o);
    }
    if ((lane & 3) == 0) {
        if (node0 < N) { g_s1s[node0] = p0; g_s1d[node0] = q0; }
        if (node1 < N) { g_s1s[node1] = p1; g_s1d[node1] = q1; }
    }
}

// scatter edges into buckets, 4 independent edges per thread for atomic MLP.
__global__ void k_fill(const int* __restrict__ ei, int E) {
    int q = (E + 3) >> 2;
    int i = blockIdx.x * blockDim.x + threadIdx.x;
    if (i >= q) return;
    int i0 = i, i1 = i + q, i2 = i + 2 * q, i3 = i + 3 * q;
    bool v1 = i1 < E, v2 = i2 < E, v3 = i3 < E;
    int s0 = ei[i0],            d0 = ei[E + i0];
    int s1 = v1 ? ei[i1] : 0,   d1 = v1 ? ei[E + i1] : 0;
    int s2 = v2 ? ei[i2] : 0,   d2 = v2 ? ei[E + i2] : 0;
    int s3 = v3 ? ei[i3] : 0,   d3 = v3 ? ei[E + i3] : 0;
    int p0 = atomicAdd(&g_cnt[d0], 1);
    int p1 = v1 ? atomicAdd(&g_cnt[d1], 1) : 0;
    int p2 = v2 ? atomicAdd(&g_cnt[d2], 1) : 0;
    int p3 = v3 ? atomicAdd(&g_cnt[d3], 1) : 0;
    if (p0 < CAP)       g_csr_src[(d0 << 7) + p0] = s0;
    if (v1 && p1 < CAP) g_csr_src[(d1 << 7) + p1] = s1;
    if (v2 && p2 < CAP) g_csr_src[(d2 << 7) + p2] = s2;
    if (v3 && p3 < CAP) g_csr_src[(d3 << 7) + p3] = s3;
}

// Layer-1 aggregation: ONE WARP per node, 2 edges per step.
// Lanes 0-15 process edge j (16B each = full 256B row), lanes 16-31 edge j+1.
__global__ void k_agg1(const float* __restrict__ b1, const float* __restrict__ W2,
                       const float* __restrict__ as2, const float* __restrict__ ad2,
                       int N) {
    int w = blockIdx.x * (blockDim.x >> 5) + (threadIdx.x >> 5);
    int lane = threadIdx.x & 31;
    if (w >= N) return;
    int base = w << 7;
    int cnt = g_cnt[w];
    float sd = g_s1d[w];
    int half = lane >> 4;
    int li = lane & 15;

    float z = 0.f;
    float a0 = 0.f, a1 = 0.f, a2 = 0.f, a3 = 0.f;
    float a4 = 0.f, a5 = 0.f, a6 = 0.f, a7 = 0.f;
    const uint4* h1v = (const uint4*)g_h1h;   // 16 x uint4 per row

    for (int c0 = 0; c0 < cnt; c0 += 32) {
        int p = c0 + lane;
        int s = 0;
        float ex = 0.f;
        if (p < cnt) {
            s = g_csr_src[base + p];
            ex = __expf(lrelu(g_s1s[s] + sd));
            z += ex;
        }
        int m = min(32, cnt - c0);
#pragma unroll 4
        for (int j = 0; j < m; j += 2) {
            int jj = j + half;                 // jj==m (odd tail) -> ex=0, harmless
            float a  = __shfl_sync(0xffffffffu, ex, jj);
            int   sj = __shfl_sync(0xffffffffu, s, jj);
            uint4 hv = h1v[sj * 16 + li];
            float2 f0 = __half22float2(*(__half2*)&hv.x);
            float2 f1 = __half22float2(*(__half2*)&hv.y);
            float2 f2 = __half22float2(*(__half2*)&hv.z);
            float2 f3 = __half22float2(*(__half2*)&hv.w);
            a0 = fmaf(a, f0.x, a0); a1 = fmaf(a, f0.y, a1);
            a2 = fmaf(a, f1.x, a2); a3 = fmaf(a, f1.y, a3);
            a4 = fmaf(a, f2.x, a4); a5 = fmaf(a, f2.y, a5);
            a6 = fmaf(a, f3.x, a6); a7 = fmaf(a, f3.y, a7);
        }
    }
    // combine the two edge-halves: feature f=li*8+k lives in lane li and lane li+16
    a0 += __shfl_xor_sync(0xffffffffu, a0, 16);
    a1 += __shfl_xor_sync(0xffffffffu, a1, 16);
    a2 += __shfl_xor_sync(0xffffffffu, a2, 16);
    a3 += __shfl_xor_sync(0xffffffffu, a3, 16);
    a4 += __shfl_xor_sync(0xffffffffu, a4, 16);
    a5 += __shfl_xor_sync(0xffffffffu, a5, 16);
    a6 += __shfl_xor_sync(0xffffffffu, a6, 16);
    a7 += __shfl_xor_sync(0xffffffffu, a7, 16);
#pragma unroll
    for (int o = 16; o > 0; o >>= 1) z += __shfl_xor_sync(0xffffffffu, z, o);

    // epilogue: features f = li*8 + {0..7}; lanes>=16 hold duplicates -> zeroed
    float4 bA = ((const float4*)b1)[li * 2 + 0];
    float4 bB = ((const float4*)b1)[li * 2 + 1];
    float g0 = fmaxf(a0 / z + bA.x, 0.f);
    float g1 = fmaxf(a1 / z + bA.y, 0.f);
    float g2 = fmaxf(a2 / z + bA.z, 0.f);
    float g3 = fmaxf(a3 / z + bA.w, 0.f);
    float g4 = fmaxf(a4 / z + bB.x, 0.f);
    float g5 = fmaxf(a5 / z + bB.y, 0.f);
    float g6 = fmaxf(a6 / z + bB.z, 0.f);
    float g7 = fmaxf(a7 / z + bB.w, 0.f);
    const float4* W24 = (const float4*)W2;    // [f][2] layout, 2 rows per float4
    float4 w0 = W24[li * 4 + 0];
    float4 w1 = W24[li * 4 + 1];
    float4 w2 = W24[li * 4 + 2];
    float4 w3 = W24[li * 4 + 3];
    float h0 = g0 * w0.x + g1 * w0.z + g2 * w1.x + g3 * w1.z
             + g4 * w2.x + g5 * w2.z + g6 * w3.x + g7 * w3.z;
    float h1 = g0 * w0.y + g1 * w0.w + g2 * w1.y + g3 * w1.w
             + g4 * w2.y + g5 * w2.w + g6 * w3.y + g7 * w3.w;
    if (half) { h0 = 0.f; h1 = 0.f; }
#pragma unroll
    for (int o = 16; o > 0; o >>= 1) {
        h0 += __shfl_down_sync(0xffffffffu, h0, o);
        h1 += __shfl_down_sync(0xffffffffu, h1, o);
    }
    if (lane == 0) {
        g_n2[w] = make_float4(h0, h1,
                              h0 * as2[0] + h1 * as2[1],
                              h0 * ad2[0] + h1 * ad2[1]);
    }
}

// Layer-2: one warp per node, single pass, packed float4 gather.
__global__ void k_agg2(const float* __restrict__ b2, float* __restrict__ out, int N) {
    int w = blockIdx.x * (blockDim.x >> 5) + (threadIdx.x >> 5);
    int lane = threadIdx.x & 31;
    if (w >= N) return;
    int base = w << 7;
    int cnt = g_cnt[w];
    float sd = g_n2[w].w;

    float z = 0.f, acc0 = 0.f, acc1 = 0.f;
    for (int p = lane; p < cnt; p += 32) {
        int s = g_csr_src[base + p];
        float4 v = g_n2[s];
        float ex = __expf(lrelu(v.z + sd));
        z += ex;
        acc0 = fmaf(ex, v.x, acc0);
        acc1 = fmaf(ex, v.y, acc1);
    }
#pragma unroll
    for (int o = 16; o > 0; o >>= 1) {
        z    += __shfl_down_sync(0xffffffffu, z, o);
        acc0 += __shfl_down_sync(0xffffffffu, acc0, o);
        acc1 += __shfl_down_sync(0xffffffffu, acc1, o);
    }
    if (lane == 0) {
        out[w * 2 + 0] = acc0 / z + b2[0];
        out[w * 2 + 1] = acc1 / z + b2[1];
    }
}

// ---------------- launch ----------------
extern "C" void kernel_launch(void* const* d_in, const int* in_sizes, int n_in,
                              void* d_out, int out_size) {
    const float* x      = (const float*)d_in[0];
    const int*   ei     = (const int*)d_in[1];
    const float* W1     = (const float*)d_in[2];
    const float* a_src1 = (const float*)d_in[3];
    const float* a_dst1 = (const float*)d_in[4];
    const float* b1     = (const float*)d_in[5];
    const float* W2     = (const float*)d_in[6];
    const float* a_src2 = (const float*)d_in[7];
    const float* a_dst2 = (const float*)d_in[8];
    const float* b2     = (const float*)d_in[9];
    float*       out    = (float*)d_out;

    int N = in_sizes[0] / F1;
    int E = in_sizes[1] / 2;

    cudaFuncSetAttribute(k_gemm1, cudaFuncAttributeMaxDynamicSharedMemorySize,
                         GEMM1_SMEM);

    k_init<<<256, 256>>>(W1, N);
    k_gemm1<<<(N + 127) / 128, 256, GEMM1_SMEM>>>(x, a_src1, a_dst1, N);
    k_fill<<<((E + 3) / 4 + 255) / 256, 256>>>(ei, E);
    k_agg1<<<(N + 7) / 8, 256>>>(b1, W2, a_src2, a_dst2, N);
    k_agg2<<<(N + 7) / 8, 256>>>(b2, out, N);
}

// round 13
// speedup vs baseline: 1.1252x; 1.1252x over previous
#include <cuda_runtime.h>
#include <cuda_fp16.h>
#include <math.h>

#define F1 128
#define MAXN 100096
#define CAP  128           // bucket capacity per node

// ---------------- static device scratch ----------------
__device__ __half g_h1h[MAXN * F1];      // fp16 projected features (gather table)
__device__ __half g_W1f[128 * 128];      // W1 fp16, pre-swizzled into mma B-fragment order
__device__ float  g_s1s[MAXN];
__device__ float  g_s1d[MAXN];
__device__ float4 g_n2[MAXN];            // packed layer-2 node data {h0, h1, s2s, s2d}
__device__ int    g_cnt[MAXN];
__device__ int    g_csr_src[MAXN * CAP];

__device__ __forceinline__ float lrelu(float e) { return fmaxf(e, 0.2f * e); }

// ---------------- kernels ----------------
// Merged init: self-loop plant + cnt=1, AND W1 fragment pre-swizzle.
__global__ void k_init(const float* __restrict__ W1, int N) {
    int i = blockIdx.x * blockDim.x + threadIdx.x;
    int stride = gridDim.x * blockDim.x;
    for (int idx = i; idx < N; idx += stride) {
        g_cnt[idx] = 1;
        g_csr_src[idx << 7] = idx;
    }
    if (i < 4096) {
        int lane = i & 31, nt = (i >> 5) & 15, ks = i >> 9;
        int kb = ks * 16 + (lane & 3) * 2;
        int n  = nt * 8 + (lane >> 2);
        __half h0 = __float2half_rn(W1[(kb + 0) * 128 + n]);
        __half h1 = __float2half_rn(W1[(kb + 1) * 128 + n]);
        __half h2 = __float2half_rn(W1[(kb + 8) * 128 + n]);
        __half h3 = __float2half_rn(W1[(kb + 9) * 128 + n]);
        __half2* out = (__half2*)g_W1f;
        out[i * 2 + 0] = __halves2half2(h0, h1);
        out[i * 2 + 1] = __halves2half2(h2, h3);
    }
}

// Tensor-core GEMM: 128 nodes x 128 out per block (256 thr, 8 warps).
#define XROW 136   // padded smem row stride in halves
#define GEMM1_SMEM (128 * XROW * 2 + 128 * 128 * 2)
__global__ void k_gemm1(const float* __restrict__ x,
                        const float* __restrict__ a_src, const float* __restrict__ a_dst,
                        int N) {
    extern __shared__ __align__(16) char dynsmem[];
    __half* sxh = (__half*)dynsmem;                    // 128*XROW halves
    __half* sW1 = (__half*)(dynsmem + 128 * XROW * 2); // 128*128 halves

    int tid = threadIdx.x;
    int nbase = blockIdx.x * 128;

    const float4* x4 = (const float4*)x;
#pragma unroll
    for (int i = 0; i < 16; i++) {
        int f = tid + 256 * i;
        int row = f >> 5, kc = (f & 31) * 4;
        int n = nbase + row;
        float4 v = (n < N) ? x4[n * 32 + (f & 31)] : make_float4(0.f, 0.f, 0.f, 0.f);
        *(__half2*)&sxh[row * XROW + kc]     = __floats2half2_rn(v.x, v.y);
        *(__half2*)&sxh[row * XROW + kc + 2] = __floats2half2_rn(v.z, v.w);
    }
    {
        const uint2* src = (const uint2*)g_W1f;
        uint2* dst = (uint2*)sW1;
#pragma unroll
        for (int i = 0; i < 16; i++) dst[tid + 256 * i] = src[tid + 256 * i];
    }
    __syncthreads();

    int w = tid >> 5, lane = tid & 31;
    int mt16 = w * 16;
    int r = lane >> 2, cq = (lane & 3) * 2;

    float c[16][4];
#pragma unroll
    for (int nt = 0; nt < 16; nt++)
#pragma unroll
        for (int j = 0; j < 4; j++) c[nt][j] = 0.f;

    const uint2* W1f2 = (const uint2*)sW1;
#pragma unroll
    for (int ks = 0; ks < 8; ks++) {
        int k0 = ks * 16;
        unsigned a0 = *(const unsigned*)&sxh[(mt16 + r) * XROW + k0 + cq];
        unsigned a1 = *(const unsigned*)&sxh[(mt16 + r + 8) * XROW + k0 + cq];
        unsigned a2 = *(const unsigned*)&sxh[(mt16 + r) * XROW + k0 + cq + 8];
        unsigned a3 = *(const unsigned*)&sxh[(mt16 + r + 8) * XROW + k0 + cq + 8];
#pragma unroll
        for (int nt = 0; nt < 16; nt++) {
            uint2 b = W1f2[(ks * 16 + nt) * 32 + lane];
            asm volatile(
                "mma.sync.aligned.m16n8k16.row.col.f32.f16.f16.f32 "
                "{%0,%1,%2,%3}, {%4,%5,%6,%7}, {%8,%9}, {%0,%1,%2,%3};"
                : "+f"(c[nt][0]), "+f"(c[nt][1]), "+f"(c[nt][2]), "+f"(c[nt][3])
                : "r"(a0), "r"(a1), "r"(a2), "r"(a3), "r"(b.x), "r"(b.y));
        }
    }

    int node0 = nbase + mt16 + r;
    int node1 = node0 + 8;
    float p0 = 0.f, q0 = 0.f, p1 = 0.f, q1 = 0.f;
    __half2* h1v = (__half2*)g_h1h;
#pragma unroll
    for (int nt = 0; nt < 16; nt++) {
        int col = nt * 8 + cq;
        float as0 = a_src[col], as1 = a_src[col + 1];
        float ad0 = a_dst[col], ad1 = a_dst[col + 1];
        p0 += c[nt][0] * as0 + c[nt][1] * as1;
        q0 += c[nt][0] * ad0 + c[nt][1] * ad1;
        p1 += c[nt][2] * as0 + c[nt][3] * as1;
        q1 += c[nt][2] * ad0 + c[nt][3] * ad1;
        if (node0 < N) h1v[node0 * 64 + (col >> 1)] = __floats2half2_rn(c[nt][0], c[nt][1]);
        if (node1 < N) h1v[node1 * 64 + (col >> 1)] = __floats2half2_rn(c[nt][2], c[nt][3]);
    }
#pragma unroll
    for (int o = 1; o <= 2; o <<= 1) {
        p0 += __shfl_xor_sync(0xffffffffu, p0, o);
        q0 += __shfl_xor_sync(0xffffffffu, q0, o);
        p1 += __shfl_xor_sync(0xffffffffu, p1, o);
        q1 += __shfl_xor_sync(0xffffffffu, q1, o);
    }
    if ((lane & 3) == 0) {
        if (node0 < N) { g_s1s[node0] = p0; g_s1d[node0] = q0; }
        if (node1 < N) { g_s1s[node1] = p1; g_s1d[node1] = q1; }
    }
}

// scatter edges into buckets, 4 independent edges per thread for atomic MLP.
__global__ void k_fill(const int* __restrict__ ei, int E) {
    int q = (E + 3) >> 2;
    int i = blockIdx.x * blockDim.x + threadIdx.x;
    if (i >= q) return;
    int i0 = i, i1 = i + q, i2 = i + 2 * q, i3 = i + 3 * q;
    bool v1 = i1 < E, v2 = i2 < E, v3 = i3 < E;
    int s0 = ei[i0],            d0 = ei[E + i0];
    int s1 = v1 ? ei[i1] : 0,   d1 = v1 ? ei[E + i1] : 0;
    int s2 = v2 ? ei[i2] : 0,   d2 = v2 ? ei[E + i2] : 0;
    int s3 = v3 ? ei[i3] : 0,   d3 = v3 ? ei[E + i3] : 0;
    int p0 = atomicAdd(&g_cnt[d0], 1);
    int p1 = v1 ? atomicAdd(&g_cnt[d1], 1) : 0;
    int p2 = v2 ? atomicAdd(&g_cnt[d2], 1) : 0;
    int p3 = v3 ? atomicAdd(&g_cnt[d3], 1) : 0;
    if (p0 < CAP)       g_csr_src[(d0 << 7) + p0] = s0;
    if (v1 && p1 < CAP) g_csr_src[(d1 << 7) + p1] = s1;
    if (v2 && p2 < CAP) g_csr_src[(d2 << 7) + p2] = s2;
    if (v3 && p3 < CAP) g_csr_src[(d3 << 7) + p3] = s3;
}

// Layer-1 aggregation: ONE WARP per node (R11 form) with warp-private smem
// staging of (row offset, exp weight) replacing the per-edge shuffles.
__global__ void k_agg1(const float* __restrict__ b1, const float* __restrict__ W2,
                       const float* __restrict__ as2, const float* __restrict__ ad2,
                       int N) {
    __shared__ uint2 sbuf[8][32];
    int wid = threadIdx.x >> 5;
    int lane = threadIdx.x & 31;
    int w = blockIdx.x * 8 + wid;
    if (w >= N) return;
    int base = w << 7;
    int cnt = g_cnt[w];
    float sd = g_s1d[w];

    float z = 0.f;
    float acc0 = 0.f, acc1 = 0.f, acc2 = 0.f, acc3 = 0.f;
    const uint2* h1v = (const uint2*)g_h1h;   // 32 x uint2 per row

    for (int c0 = 0; c0 < cnt; c0 += 32) {
        int p = c0 + lane;
        unsigned soff = 0;
        float ex = 0.f;
        if (p < cnt) {
            int s = g_csr_src[base + p];
            ex = __expf(lrelu(g_s1s[s] + sd));
            z += ex;
            soff = (unsigned)s * 32u;          // premultiplied uint2 row offset
        }
        sbuf[wid][lane] = make_uint2(soff, __float_as_uint(ex));
        __syncwarp();
        int m = min(32, cnt - c0);
#pragma unroll 8
        for (int j = 0; j < m; j++) {
            uint2 se = sbuf[wid][j];           // broadcast LDS.64
            float a = __uint_as_float(se.y);
            uint2 hv = __ldg(&h1v[se.x + lane]);
            float2 f01 = __half22float2(*(__half2*)&hv.x);
            float2 f23 = __half22float2(*(__half2*)&hv.y);
            acc0 = fmaf(a, f01.x, acc0);
            acc1 = fmaf(a, f01.y, acc1);
            acc2 = fmaf(a, f23.x, acc2);
            acc3 = fmaf(a, f23.y, acc3);
        }
        __syncwarp();
    }
#pragma unroll
    for (int o = 16; o > 0; o >>= 1) z += __shfl_xor_sync(0xffffffffu, z, o);

    // epilogue: features f = lane*4 + {0..3}
    float4 bv = ((const float4*)b1)[lane];
    float g0 = fmaxf(acc0 / z + bv.x, 0.f);
    float g1 = fmaxf(acc1 / z + bv.y, 0.f);
    float g2 = fmaxf(acc2 / z + bv.z, 0.f);
    float g3 = fmaxf(acc3 / z + bv.w, 0.f);
    const float4* W24 = (const float4*)W2;
    float4 wA = W24[lane * 2 + 0];
    float4 wB = W24[lane * 2 + 1];
    float h0 = g0 * wA.x + g1 * wA.z + g2 * wB.x + g3 * wB.z;
    float h1 = g0 * wA.y + g1 * wA.w + g2 * wB.y + g3 * wB.w;
#pragma unroll
    for (int o = 16; o > 0; o >>= 1) {
        h0 += __shfl_down_sync(0xffffffffu, h0, o);
        h1 += __shfl_down_sync(0xffffffffu, h1, o);
    }
    if (lane == 0) {
        g_n2[w] = make_float4(h0, h1,
                              h0 * as2[0] + h1 * as2[1],
                              h0 * ad2[0] + h1 * ad2[1]);
    }
}

// Layer-2: one warp per node, single pass, packed float4 gather.
__global__ void k_agg2(const float* __restrict__ b2, float* __restrict__ out, int N) {
    int w = blockIdx.x * (blockDim.x >> 5) + (threadIdx.x >> 5);
    int lane = threadIdx.x & 31;
    if (w >= N) return;
    int base = w << 7;
    int cnt = g_cnt[w];
    float sd = g_n2[w].w;

    float z = 0.f, acc0 = 0.f, acc1 = 0.f;
    for (int p = lane; p < cnt; p += 32) {
        int s = g_csr_src[base + p];
        float4 v = g_n2[s];
        float ex = __expf(lrelu(v.z + sd));
        z += ex;
        acc0 = fmaf(ex, v.x, acc0);
        acc1 = fmaf(ex, v.y, acc1);
    }
#pragma unroll
    for (int o = 16; o > 0; o >>= 1) {
        z    += __shfl_down_sync(0xffffffffu, z, o);
        acc0 += __shfl_down_sync(0xffffffffu, acc0, o);
        acc1 += __shfl_down_sync(0xffffffffu, acc1, o);
    }
    if (lane == 0) {
        out[w * 2 + 0] = acc0 / z + b2[0];
        out[w * 2 + 1] = acc1 / z + b2[1];
    }
}

// ---------------- launch ----------------
extern "C" void kernel_launch(void* const* d_in, const int* in_sizes, int n_in,
                              void* d_out, int out_size) {
    const float* x      = (const float*)d_in[0];
    const int*   ei     = (const int*)d_in[1];
    const float* W1     = (const float*)d_in[2];
    const float* a_src1 = (const float*)d_in[3];
    const float* a_dst1 = (const float*)d_in[4];
    const float* b1     = (const float*)d_in[5];
    const float* W2     = (const float*)d_in[6];
    const float* a_src2 = (const float*)d_in[7];
    const float* a_dst2 = (const float*)d_in[8];
    const float* b2     = (const float*)d_in[9];
    float*       out    = (float*)d_out;

    int N = in_sizes[0] / F1;
    int E = in_sizes[1] / 2;

    cudaFuncSetAttribute(k_gemm1, cudaFuncAttributeMaxDynamicSharedMemorySize,
                         GEMM1_SMEM);

    k_init<<<256, 256>>>(W1, N);
    k_gemm1<<<(N + 127) / 128, 256, GEMM1_SMEM>>>(x, a_src1, a_dst1, N);
    k_fill<<<((E + 3) / 4 + 255) / 256, 256>>>(ei, E);
    k_agg1<<<(N + 7) / 8, 256>>>(b1, W2, a_src2, a_dst2, N);
    k_agg2<<<(N + 7) / 8, 256>>>(b2, out, N);
}

// round 14
// speedup vs baseline: 1.2206x; 1.0848x over previous
#include <cuda_runtime.h>
#include <cuda_fp16.h>
#include <math.h>

#define F1 128
#define MAXN 100096
#define CAP  128           // bucket capacity per node

// ---------------- static device scratch ----------------
__device__ __half g_h1h[MAXN * F1];      // fp16 projected features (gather table)
__device__ __half g_W1f[128 * 128];      // W1 fp16, pre-swizzled into mma B-fragment order
__device__ float  g_s1s[MAXN];
__device__ float  g_s1d[MAXN];
__device__ float4 g_n2[MAXN];            // packed layer-2 node data {h0, h1, s2s, s2d}
__device__ int    g_cnt[MAXN];
__device__ int    g_csr_src[MAXN * CAP];

__device__ __forceinline__ float lrelu(float e) { return fmaxf(e, 0.2f * e); }

// ---------------- kernels ----------------
// Merged init: self-loop plant + cnt=1, AND W1 fragment pre-swizzle.
__global__ void k_init(const float* __restrict__ W1, int N) {
    int i = blockIdx.x * blockDim.x + threadIdx.x;
    int stride = gridDim.x * blockDim.x;
    for (int idx = i; idx < N; idx += stride) {
        g_cnt[idx] = 1;
        g_csr_src[idx << 7] = idx;
    }
    if (i < 4096) {
        int lane = i & 31, nt = (i >> 5) & 15, ks = i >> 9;
        int kb = ks * 16 + (lane & 3) * 2;
        int n  = nt * 8 + (lane >> 2);
        __half h0 = __float2half_rn(W1[(kb + 0) * 128 + n]);
        __half h1 = __float2half_rn(W1[(kb + 1) * 128 + n]);
        __half h2 = __float2half_rn(W1[(kb + 8) * 128 + n]);
        __half h3 = __float2half_rn(W1[(kb + 9) * 128 + n]);
        __half2* out = (__half2*)g_W1f;
        out[i * 2 + 0] = __halves2half2(h0, h1);
        out[i * 2 + 1] = __halves2half2(h2, h3);
    }
}

// Tensor-core GEMM: 128 nodes x 128 out per block (256 thr, 8 warps).
#define XROW 136   // padded smem row stride in halves
#define GEMM1_SMEM (128 * XROW * 2 + 128 * 128 * 2)
__global__ void k_gemm1(const float* __restrict__ x,
                        const float* __restrict__ a_src, const float* __restrict__ a_dst,
                        int N) {
    extern __shared__ __align__(16) char dynsmem[];
    __half* sxh = (__half*)dynsmem;                    // 128*XROW halves
    __half* sW1 = (__half*)(dynsmem + 128 * XROW * 2); // 128*128 halves

    int tid = threadIdx.x;
    int nbase = blockIdx.x * 128;

    const float4* x4 = (const float4*)x;
#pragma unroll
    for (int i = 0; i < 16; i++) {
        int f = tid + 256 * i;
        int row = f >> 5, kc = (f & 31) * 4;
        int n = nbase + row;
        float4 v = (n < N) ? x4[n * 32 + (f & 31)] : make_float4(0.f, 0.f, 0.f, 0.f);
        *(__half2*)&sxh[row * XROW + kc]     = __floats2half2_rn(v.x, v.y);
        *(__half2*)&sxh[row * XROW + kc + 2] = __floats2half2_rn(v.z, v.w);
    }
    {
        const uint2* src = (const uint2*)g_W1f;
        uint2* dst = (uint2*)sW1;
#pragma unroll
        for (int i = 0; i < 16; i++) dst[tid + 256 * i] = src[tid + 256 * i];
    }
    __syncthreads();

    int w = tid >> 5, lane = tid & 31;
    int mt16 = w * 16;
    int r = lane >> 2, cq = (lane & 3) * 2;

    float c[16][4];
#pragma unroll
    for (int nt = 0; nt < 16; nt++)
#pragma unroll
        for (int j = 0; j < 4; j++) c[nt][j] = 0.f;

    const uint2* W1f2 = (const uint2*)sW1;
#pragma unroll
    for (int ks = 0; ks < 8; ks++) {
        int k0 = ks * 16;
        unsigned a0 = *(const unsigned*)&sxh[(mt16 + r) * XROW + k0 + cq];
        unsigned a1 = *(const unsigned*)&sxh[(mt16 + r + 8) * XROW + k0 + cq];
        unsigned a2 = *(const unsigned*)&sxh[(mt16 + r) * XROW + k0 + cq + 8];
        unsigned a3 = *(const unsigned*)&sxh[(mt16 + r + 8) * XROW + k0 + cq + 8];
#pragma unroll
        for (int nt = 0; nt < 16; nt++) {
            uint2 b = W1f2[(ks * 16 + nt) * 32 + lane];
            asm volatile(
                "mma.sync.aligned.m16n8k16.row.col.f32.f16.f16.f32 "
                "{%0,%1,%2,%3}, {%4,%5,%6,%7}, {%8,%9}, {%0,%1,%2,%3};"
                : "+f"(c[nt][0]), "+f"(c[nt][1]), "+f"(c[nt][2]), "+f"(c[nt][3])
                : "r"(a0), "r"(a1), "r"(a2), "r"(a3), "r"(b.x), "r"(b.y));
        }
    }

    int node0 = nbase + mt16 + r;
    int node1 = node0 + 8;
    float p0 = 0.f, q0 = 0.f, p1 = 0.f, q1 = 0.f;
    __half2* h1v = (__half2*)g_h1h;
#pragma unroll
    for (int nt = 0; nt < 16; nt++) {
        int col = nt * 8 + cq;
        float as0 = a_src[col], as1 = a_src[col + 1];
        float ad0 = a_dst[col], ad1 = a_dst[col + 1];
        p0 += c[nt][0] * as0 + c[nt][1] * as1;
        q0 += c[nt][0] * ad0 + c[nt][1] * ad1;
        p1 += c[nt][2] * as0 + c[nt][3] * as1;
        q1 += c[nt][2] * ad0 + c[nt][3] * ad1;
        if (node0 < N) h1v[node0 * 64 + (col >> 1)] = __floats2half2_rn(c[nt][0], c[nt][1]);
        if (node1 < N) h1v[node1 * 64 + (col >> 1)] = __floats2half2_rn(c[nt][2], c[nt][3]);
    }
#pragma unroll
    for (int o = 1; o <= 2; o <<= 1) {
        p0 += __shfl_xor_sync(0xffffffffu, p0, o);
        q0 += __shfl_xor_sync(0xffffffffu, q0, o);
        p1 += __shfl_xor_sync(0xffffffffu, p1, o);
        q1 += __shfl_xor_sync(0xffffffffu, q1, o);
    }
    if ((lane & 3) == 0) {
        if (node0 < N) { g_s1s[node0] = p0; g_s1d[node0] = q0; }
        if (node1 < N) { g_s1s[node1] = p1; g_s1d[node1] = q1; }
    }
}

// scatter edges into buckets, 4 independent edges per thread for atomic MLP.
__global__ void k_fill(const int* __restrict__ ei, int E) {
    int q = (E + 3) >> 2;
    int i = blockIdx.x * blockDim.x + threadIdx.x;
    if (i >= q) return;
    int i0 = i, i1 = i + q, i2 = i + 2 * q, i3 = i + 3 * q;
    bool v1 = i1 < E, v2 = i2 < E, v3 = i3 < E;
    int s0 = ei[i0],            d0 = ei[E + i0];
    int s1 = v1 ? ei[i1] : 0,   d1 = v1 ? ei[E + i1] : 0;
    int s2 = v2 ? ei[i2] : 0,   d2 = v2 ? ei[E + i2] : 0;
    int s3 = v3 ? ei[i3] : 0,   d3 = v3 ? ei[E + i3] : 0;
    int p0 = atomicAdd(&g_cnt[d0], 1);
    int p1 = v1 ? atomicAdd(&g_cnt[d1], 1) : 0;
    int p2 = v2 ? atomicAdd(&g_cnt[d2], 1) : 0;
    int p3 = v3 ? atomicAdd(&g_cnt[d3], 1) : 0;
    if (p0 < CAP)       g_csr_src[(d0 << 7) + p0] = s0;
    if (v1 && p1 < CAP) g_csr_src[(d1 << 7) + p1] = s1;
    if (v2 && p2 < CAP) g_csr_src[(d2 << 7) + p2] = s2;
    if (v3 && p3 < CAP) g_csr_src[(d3 << 7) + p3] = s3;
}

// Layer-1 aggregation: ONE WARP per node, warp-private smem staging of
// (premultiplied row offset, exp weight); fused relu(+b1)@W2 epilogue.
__global__ void k_agg1(const float* __restrict__ b1, const float* __restrict__ W2,
                       const float* __restrict__ as2, const float* __restrict__ ad2,
                       int N) {
    __shared__ uint2 sbuf[8][32];
    int wid = threadIdx.x >> 5;
    int lane = threadIdx.x & 31;
    int w = blockIdx.x * 8 + wid;
    if (w >= N) return;
    int base = w << 7;
    int cnt = g_cnt[w];
    float sd = g_s1d[w];

    float z = 0.f;
    float acc0 = 0.f, acc1 = 0.f, acc2 = 0.f, acc3 = 0.f;
    const uint2* h1v = (const uint2*)g_h1h;   // 32 x uint2 per row

    for (int c0 = 0; c0 < cnt; c0 += 32) {
        int p = c0 + lane;
        unsigned soff = 0;
        float ex = 0.f;
        if (p < cnt) {
            int s = g_csr_src[base + p];
            ex = __expf(lrelu(g_s1s[s] + sd));
            z += ex;
            soff = (unsigned)s * 32u;          // premultiplied uint2 row offset
        }
        sbuf[wid][lane] = make_uint2(soff, __float_as_uint(ex));
        __syncwarp();
        int m = min(32, cnt - c0);
#pragma unroll 8
        for (int j = 0; j < m; j++) {
            uint2 se = sbuf[wid][j];           // broadcast LDS.64
            float a = __uint_as_float(se.y);
            uint2 hv = __ldg(&h1v[se.x + lane]);
            float2 f01 = __half22float2(*(__half2*)&hv.x);
            float2 f23 = __half22float2(*(__half2*)&hv.y);
            acc0 = fmaf(a, f01.x, acc0);
            acc1 = fmaf(a, f01.y, acc1);
            acc2 = fmaf(a, f23.x, acc2);
            acc3 = fmaf(a, f23.y, acc3);
        }
        __syncwarp();
    }
#pragma unroll
    for (int o = 16; o > 0; o >>= 1) z += __shfl_xor_sync(0xffffffffu, z, o);

    // epilogue: features f = lane*4 + {0..3}
    float4 bv = ((const float4*)b1)[lane];
    float g0 = fmaxf(acc0 / z + bv.x, 0.f);
    float g1 = fmaxf(acc1 / z + bv.y, 0.f);
    float g2 = fmaxf(acc2 / z + bv.z, 0.f);
    float g3 = fmaxf(acc3 / z + bv.w, 0.f);
    const float4* W24 = (const float4*)W2;
    float4 wA = W24[lane * 2 + 0];
    float4 wB = W24[lane * 2 + 1];
    float h0 = g0 * wA.x + g1 * wA.z + g2 * wB.x + g3 * wB.z;
    float h1 = g0 * wA.y + g1 * wA.w + g2 * wB.y + g3 * wB.w;
#pragma unroll
    for (int o = 16; o > 0; o >>= 1) {
        h0 += __shfl_down_sync(0xffffffffu, h0, o);
        h1 += __shfl_down_sync(0xffffffffu, h1, o);
    }
    if (lane == 0) {
        g_n2[w] = make_float4(h0, h1,
                              h0 * as2[0] + h1 * as2[1],
                              h0 * ad2[0] + h1 * ad2[1]);
    }
}

// Layer-2: EIGHT lanes per node (4 nodes per warp) — cuts idle lanes and warp
// count 4x; reduction is 3 xor-shuffles within the 8-lane group.
__global__ void k_agg2(const float* __restrict__ b2, float* __restrict__ out, int N) {
    int g = (blockIdx.x * blockDim.x + threadIdx.x) >> 3;   // global 8-lane group
    int li = threadIdx.x & 7;
    if (g >= N) return;
    int base = g << 7;
    int cnt = g_cnt[g];
    float sd = g_n2[g].w;

    float z = 0.f, acc0 = 0.f, acc1 = 0.f;
    for (int p = li; p < cnt; p += 8) {
        int s = g_csr_src[base + p];
        float4 v = g_n2[s];
        float ex = __expf(lrelu(v.z + sd));
        z += ex;
        acc0 = fmaf(ex, v.x, acc0);
        acc1 = fmaf(ex, v.y, acc1);
    }
#pragma unroll
    for (int o = 4; o > 0; o >>= 1) {
        z    += __shfl_xor_sync(0xffffffffu, z, o);
        acc0 += __shfl_xor_sync(0xffffffffu, acc0, o);
        acc1 += __shfl_xor_sync(0xffffffffu, acc1, o);
    }
    if (li == 0) {
        out[g * 2 + 0] = acc0 / z + b2[0];
        out[g * 2 + 1] = acc1 / z + b2[1];
    }
}

// ---------------- launch ----------------
extern "C" void kernel_launch(void* const* d_in, const int* in_sizes, int n_in,
                              void* d_out, int out_size) {
    const float* x      = (const float*)d_in[0];
    const int*   ei     = (const int*)d_in[1];
    const float* W1     = (const float*)d_in[2];
    const float* a_src1 = (const float*)d_in[3];
    const float* a_dst1 = (const float*)d_in[4];
    const float* b1     = (const float*)d_in[5];
    const float* W2     = (const float*)d_in[6];
    const float* a_src2 = (const float*)d_in[7];
    const float* a_dst2 = (const float*)d_in[8];
    const float* b2     = (const float*)d_in[9];
    float*       out    = (float*)d_out;

    int N = in_sizes[0] / F1;
    int E = in_sizes[1] / 2;

    cudaFuncSetAttribute(k_gemm1, cudaFuncAttributeMaxDynamicSharedMemorySize,
                         GEMM1_SMEM);

    k_init<<<256, 256>>>(W1, N);
    k_gemm1<<<(N + 127) / 128, 256, GEMM1_SMEM>>>(x, a_src1, a_dst1, N);
    k_fill<<<((E + 3) / 4 + 255) / 256, 256>>>(ei, E);
    k_agg1<<<(N + 7) / 8, 256>>>(b1, W2, a_src2, a_dst2, N);
    k_agg2<<<(N * 8 + 255) / 256, 256>>>(b2, out, N);
}

// round 16
// speedup vs baseline: 1.2641x; 1.0356x over previous
#include <cuda_runtime.h>
#include <cuda_fp16.h>
#include <math.h>

#define F1 128
#define MAXN 100096
#define CAP  128           // bucket capacity per node

// ---------------- static device scratch ----------------
__device__ __half g_h1h[MAXN * F1];      // fp16 projected features (gather table)
__device__ __half g_W1f[128 * 128];      // W1 fp16, pre-swizzled into mma B-fragment order
__device__ float  g_s1s[MAXN];
__device__ float  g_s1d[MAXN];
__device__ float4 g_n2[MAXN];            // packed layer-2 node data {h0, h1, s2s, s2d}
__device__ int    g_cnt[MAXN];
__device__ int    g_csr_src[MAXN * CAP];

__device__ __forceinline__ float lrelu(float e) { return fmaxf(e, 0.2f * e); }

// ---------------- kernels ----------------
// Merged init: self-loop plant + cnt=1, AND W1 fragment pre-swizzle.
__global__ void k_init(const float* __restrict__ W1, int N) {
    int i = blockIdx.x * blockDim.x + threadIdx.x;
    int stride = gridDim.x * blockDim.x;
    for (int idx = i; idx < N; idx += stride) {
        g_cnt[idx] = 1;
        g_csr_src[idx << 7] = idx;
    }
    if (i < 4096) {
        int lane = i & 31, nt = (i >> 5) & 15, ks = i >> 9;
        int kb = ks * 16 + (lane & 3) * 2;
        int n  = nt * 8 + (lane >> 2);
        __half h0 = __float2half_rn(W1[(kb + 0) * 128 + n]);
        __half h1 = __float2half_rn(W1[(kb + 1) * 128 + n]);
        __half h2 = __float2half_rn(W1[(kb + 8) * 128 + n]);
        __half h3 = __float2half_rn(W1[(kb + 9) * 128 + n]);
        __half2* out = (__half2*)g_W1f;
        out[i * 2 + 0] = __halves2half2(h0, h1);
        out[i * 2 + 1] = __halves2half2(h2, h3);
    }
}

// Fused phase 1: blocks [0,G) run tensor-core GEMM (128 nodes x 128 out,
// 256 thr, 8 warps); blocks [G, G+F) scatter edges into CSR buckets
// (4 independent edges per thread for atomic MLP). The two halves touch
// disjoint state, so they overlap inside one launch.
#define XROW 136   // padded smem row stride in halves
#define GEMM1_SMEM (128 * XROW * 2 + 128 * 128 * 2)
__global__ void k_phase1(const float* __restrict__ x,
                         const float* __restrict__ a_src, const float* __restrict__ a_dst,
                         const int* __restrict__ ei,
                         int N, int E, int G) {
    if (blockIdx.x >= G) {
        // ---- fill body ----
        int q = (E + 3) >> 2;
        int i = (blockIdx.x - G) * blockDim.x + threadIdx.x;
        if (i >= q) return;
        int i0 = i, i1 = i + q, i2 = i + 2 * q, i3 = i + 3 * q;
        bool v1 = i1 < E, v2 = i2 < E, v3 = i3 < E;
        int s0 = ei[i0],            d0 = ei[E + i0];
        int s1 = v1 ? ei[i1] : 0,   d1 = v1 ? ei[E + i1] : 0;
        int s2 = v2 ? ei[i2] : 0,   d2 = v2 ? ei[E + i2] : 0;
        int s3 = v3 ? ei[i3] : 0,   d3 = v3 ? ei[E + i3] : 0;
        int p0 = atomicAdd(&g_cnt[d0], 1);
        int p1 = v1 ? atomicAdd(&g_cnt[d1], 1) : 0;
        int p2 = v2 ? atomicAdd(&g_cnt[d2], 1) : 0;
        int p3 = v3 ? atomicAdd(&g_cnt[d3], 1) : 0;
        if (p0 < CAP)       g_csr_src[(d0 << 7) + p0] = s0;
        if (v1 && p1 < CAP) g_csr_src[(d1 << 7) + p1] = s1;
        if (v2 && p2 < CAP) g_csr_src[(d2 << 7) + p2] = s2;
        if (v3 && p3 < CAP) g_csr_src[(d3 << 7) + p3] = s3;
        return;
    }

    // ---- gemm1 body ----
    extern __shared__ __align__(16) char dynsmem[];
    __half* sxh = (__half*)dynsmem;                    // 128*XROW halves
    __half* sW1 = (__half*)(dynsmem + 128 * XROW * 2); // 128*128 halves

    int tid = threadIdx.x;
    int nbase = blockIdx.x * 128;

    const float4* x4 = (const float4*)x;
#pragma unroll
    for (int i = 0; i < 16; i++) {
        int f = tid + 256 * i;
        int row = f >> 5, kc = (f & 31) * 4;
        int n = nbase + row;
        float4 v = (n < N) ? x4[n * 32 + (f & 31)] : make_float4(0.f, 0.f, 0.f, 0.f);
        *(__half2*)&sxh[row * XROW + kc]     = __floats2half2_rn(v.x, v.y);
        *(__half2*)&sxh[row * XROW + kc + 2] = __floats2half2_rn(v.z, v.w);
    }
    {
        const uint2* src = (const uint2*)g_W1f;
        uint2* dst = (uint2*)sW1;
#pragma unroll
        for (int i = 0; i < 16; i++) dst[tid + 256 * i] = src[tid + 256 * i];
    }
    __syncthreads();

    int w = tid >> 5, lane = tid & 31;
    int mt16 = w * 16;
    int r = lane >> 2, cq = (lane & 3) * 2;

    float c[16][4];
#pragma unroll
    for (int nt = 0; nt < 16; nt++)
#pragma unroll
        for (int j = 0; j < 4; j++) c[nt][j] = 0.f;

    const uint2* W1f2 = (const uint2*)sW1;
#pragma unroll
    for (int ks = 0; ks < 8; ks++) {
        int k0 = ks * 16;
        unsigned a0 = *(const unsigned*)&sxh[(mt16 + r) * XROW + k0 + cq];
        unsigned a1 = *(const unsigned*)&sxh[(mt16 + r + 8) * XROW + k0 + cq];
        unsigned a2 = *(const unsigned*)&sxh[(mt16 + r) * XROW + k0 + cq + 8];
        unsigned a3 = *(const unsigned*)&sxh[(mt16 + r + 8) * XROW + k0 + cq + 8];
#pragma unroll
        for (int nt = 0; nt < 16; nt++) {
            uint2 b = W1f2[(ks * 16 + nt) * 32 + lane];
            asm volatile(
                "mma.sync.aligned.m16n8k16.row.col.f32.f16.f16.f32 "
                "{%0,%1,%2,%3}, {%4,%5,%6,%7}, {%8,%9}, {%0,%1,%2,%3};"
                : "+f"(c[nt][0]), "+f"(c[nt][1]), "+f"(c[nt][2]), "+f"(c[nt][3])
                : "r"(a0), "r"(a1), "r"(a2), "r"(a3), "r"(b.x), "r"(b.y));
        }
    }

    int node0 = nbase + mt16 + r;
    int node1 = node0 + 8;
    float p0 = 0.f, q0 = 0.f, p1 = 0.f, q1 = 0.f;
    __half2* h1v = (__half2*)g_h1h;
#pragma unroll
    for (int nt = 0; nt < 16; nt++) {
        int col = nt * 8 + cq;
        float as0 = a_src[col], as1 = a_src[col + 1];
        float ad0 = a_dst[col], ad1 = a_dst[col + 1];
        p0 += c[nt][0] * as0 + c[nt][1] * as1;
        q0 += c[nt][0] * ad0 + c[nt][1] * ad1;
        p1 += c[nt][2] * as0 + c[nt][3] * as1;
        q1 += c[nt][2] * ad0 + c[nt][3] * ad1;
        if (node0 < N) h1v[node0 * 64 + (col >> 1)] = __floats2half2_rn(c[nt][0], c[nt][1]);
        if (node1 < N) h1v[node1 * 64 + (col >> 1)] = __floats2half2_rn(c[nt][2], c[nt][3]);
    }
#pragma unroll
    for (int o = 1; o <= 2; o <<= 1) {
        p0 += __shfl_xor_sync(0xffffffffu, p0, o);
        q0 += __shfl_xor_sync(0xffffffffu, q0, o);
        p1 += __shfl_xor_sync(0xffffffffu, p1, o);
        q1 += __shfl_xor_sync(0xffffffffu, q1, o);
    }
    if ((lane & 3) == 0) {
        if (node0 < N) { g_s1s[node0] = p0; g_s1d[node0] = q0; }
        if (node1 < N) { g_s1s[node1] = p1; g_s1d[node1] = q1; }
    }
}

// Layer-1 aggregation: ONE WARP per node, warp-private smem staging of
// (premultiplied row offset, exp weight); fused relu(+b1)@W2 epilogue.
__global__ void k_agg1(const float* __restrict__ b1, const float* __restrict__ W2,
                       const float* __restrict__ as2, const float* __restrict__ ad2,
                       int N) {
    __shared__ uint2 sbuf[8][32];
    int wid = threadIdx.x >> 5;
    int lane = threadIdx.x & 31;
    int w = blockIdx.x * 8 + wid;
    if (w >= N) return;
    int base = w << 7;
    int cnt = g_cnt[w];
    float sd = g_s1d[w];

    float z = 0.f;
    float acc0 = 0.f, acc1 = 0.f, acc2 = 0.f, acc3 = 0.f;
    const uint2* h1v = (const uint2*)g_h1h;   // 32 x uint2 per row

    for (int c0 = 0; c0 < cnt; c0 += 32) {
        int p = c0 + lane;
        unsigned soff = 0;
        float ex = 0.f;
        if (p < cnt) {
            int s = g_csr_src[base + p];
            ex = __expf(lrelu(g_s1s[s] + sd));
            z += ex;
            soff = (unsigned)s * 32u;          // premultiplied uint2 row offset
        }
        sbuf[wid][lane] = make_uint2(soff, __float_as_uint(ex));
        __syncwarp();
        int m = min(32, cnt - c0);
#pragma unroll 8
        for (int j = 0; j < m; j++) {
            uint2 se = sbuf[wid][j];           // broadcast LDS.64
            float a = __uint_as_float(se.y);
            uint2 hv = __ldg(&h1v[se.x + lane]);
            float2 f01 = __half22float2(*(__half2*)&hv.x);
            float2 f23 = __half22float2(*(__half2*)&hv.y);
            acc0 = fmaf(a, f01.x, acc0);
            acc1 = fmaf(a, f01.y, acc1);
            acc2 = fmaf(a, f23.x, acc2);
            acc3 = fmaf(a, f23.y, acc3);
        }
        __syncwarp();
    }
#pragma unroll
    for (int o = 16; o > 0; o >>= 1) z += __shfl_xor_sync(0xffffffffu, z, o);

    // epilogue: features f = lane*4 + {0..3}
    float4 bv = ((const float4*)b1)[lane];
    float g0 = fmaxf(acc0 / z + bv.x, 0.f);
    float g1 = fmaxf(acc1 / z + bv.y, 0.f);
    float g2 = fmaxf(acc2 / z + bv.z, 0.f);
    float g3 = fmaxf(acc3 / z + bv.w, 0.f);
    const float4* W24 = (const float4*)W2;
    float4 wA = W24[lane * 2 + 0];
    float4 wB = W24[lane * 2 + 1];
    float h0 = g0 * wA.x + g1 * wA.z + g2 * wB.x + g3 * wB.z;
    float h1 = g0 * wA.y + g1 * wA.w + g2 * wB.y + g3 * wB.w;
#pragma unroll
    for (int o = 16; o > 0; o >>= 1) {
        h0 += __shfl_down_sync(0xffffffffu, h0, o);
        h1 += __shfl_down_sync(0xffffffffu, h1, o);
    }
    if (lane == 0) {
        g_n2[w] = make_float4(h0, h1,
                              h0 * as2[0] + h1 * as2[1],
                              h0 * ad2[0] + h1 * ad2[1]);
    }
}

// Layer-2: EIGHT lanes per node (4 nodes per warp).
__global__ void k_agg2(const float* __restrict__ b2, float* __restrict__ out, int N) {
    int g = (blockIdx.x * blockDim.x + threadIdx.x) >> 3;   // global 8-lane group
    int li = threadIdx.x & 7;
    if (g >= N) return;
    int base = g << 7;
    int cnt = g_cnt[g];
    float sd = g_n2[g].w;

    float z = 0.f, acc0 = 0.f, acc1 = 0.f;
    for (int p = li; p < cnt; p += 8) {
        int s = g_csr_src[base + p];
        float4 v = g_n2[s];
        float ex = __expf(lrelu(v.z + sd));
        z += ex;
        acc0 = fmaf(ex, v.x, acc0);
        acc1 = fmaf(ex, v.y, acc1);
    }
#pragma unroll
    for (int o = 4; o > 0; o >>= 1) {
        z    += __shfl_xor_sync(0xffffffffu, z, o);
        acc0 += __shfl_xor_sync(0xffffffffu, acc0, o);
        acc1 += __shfl_xor_sync(0xffffffffu, acc1, o);
    }
    if (li == 0) {
        out[g * 2 + 0] = acc0 / z + b2[0];
        out[g * 2 + 1] = acc1 / z + b2[1];
    }
}

// ---------------- launch ----------------
extern "C" void kernel_launch(void* const* d_in, const int* in_sizes, int n_in,
                              void* d_out, int out_size) {
    const float* x      = (const float*)d_in[0];
    const int*   ei     = (const int*)d_in[1];
    const float* W1     = (const float*)d_in[2];
    const float* a_src1 = (const float*)d_in[3];
    const float* a_dst1 = (const float*)d_in[4];
    const float* b1     = (const float*)d_in[5];
    const float* W2     = (const float*)d_in[6];
    const float* a_src2 = (const float*)d_in[7];
    const float* a_dst2 = (const float*)d_in[8];
    const float* b2     = (const float*)d_in[9];
    float*       out    = (float*)d_out;

    int N = in_sizes[0] / F1;
    int E = in_sizes[1] / 2;
    int G = (N + 127) / 128;                       // gemm1 blocks
    int F = ((E + 3) / 4 + 255) / 256;             // fill blocks

    cudaFuncSetAttribute(k_phase1, cudaFuncAttributeMaxDynamicSharedMemorySize,
                         GEMM1_SMEM);

    k_init<<<256, 256>>>(W1, N);
    k_phase1<<<G + F, 256, GEMM1_SMEM>>>(x, a_src1, a_dst1, ei, N, E, G);
    k_agg1<<<(N + 7) / 8, 256>>>(b1, W2, a_src2, a_dst2, N);
    k_agg2<<<(N * 8 + 255) / 256, 256>>>(b2, out, N);
}

// round 17
// speedup vs baseline: 1.2656x; 1.0012x over previous
#include <cuda_runtime.h>
#include <cuda_fp16.h>
#include <math.h>

#define F1 128
#define MAXN 100096
#define CAP  128           // bucket capacity per node (real degree only now)

// ---------------- static device scratch ----------------
__device__ __half g_h1h[MAXN * F1];      // fp16 projected features (gather table)
__device__ __half g_W1f[128 * 128];      // W1 fp16, pre-swizzled into mma B-fragment order
__device__ float  g_s1s[MAXN];
__device__ float  g_s1d[MAXN];
__device__ float4 g_n2[MAXN];            // packed layer-2 node data {h0, h1, s2s, s2d}
__device__ int    g_cnt[MAXN];
__device__ int    g_csr_src[MAXN * CAP];

__device__ __forceinline__ float lrelu(float e) { return fmaxf(e, 0.2f * e); }

// ---------------- kernels ----------------
// Init: zero cnt (self-loop handled analytically in agg kernels) + W1 prep.
__global__ void k_init(const float* __restrict__ W1, int N) {
    int i = blockIdx.x * blockDim.x + threadIdx.x;
    int stride = gridDim.x * blockDim.x;
    for (int idx = i; idx < N; idx += stride) g_cnt[idx] = 0;
    if (i < 4096) {
        int lane = i & 31, nt = (i >> 5) & 15, ks = i >> 9;
        int kb = ks * 16 + (lane & 3) * 2;
        int n  = nt * 8 + (lane >> 2);
        __half h0 = __float2half_rn(W1[(kb + 0) * 128 + n]);
        __half h1 = __float2half_rn(W1[(kb + 1) * 128 + n]);
        __half h2 = __float2half_rn(W1[(kb + 8) * 128 + n]);
        __half h3 = __float2half_rn(W1[(kb + 9) * 128 + n]);
        __half2* out = (__half2*)g_W1f;
        out[i * 2 + 0] = __halves2half2(h0, h1);
        out[i * 2 + 1] = __halves2half2(h2, h3);
    }
}

// Fused phase 1: blocks [0,G) tensor-core GEMM; blocks [G,G+F) CSR fill.
#define XROW 136   // padded smem row stride in halves
#define GEMM1_SMEM (128 * XROW * 2 + 128 * 128 * 2)
__global__ void k_phase1(const float* __restrict__ x,
                         const float* __restrict__ a_src, const float* __restrict__ a_dst,
                         const int* __restrict__ ei,
                         int N, int E, int G) {
    if (blockIdx.x >= G) {
        // ---- fill body ----
        int q = (E + 3) >> 2;
        int i = (blockIdx.x - G) * blockDim.x + threadIdx.x;
        if (i >= q) return;
        int i0 = i, i1 = i + q, i2 = i + 2 * q, i3 = i + 3 * q;
        bool v1 = i1 < E, v2 = i2 < E, v3 = i3 < E;
        int s0 = ei[i0],            d0 = ei[E + i0];
        int s1 = v1 ? ei[i1] : 0,   d1 = v1 ? ei[E + i1] : 0;
        int s2 = v2 ? ei[i2] : 0,   d2 = v2 ? ei[E + i2] : 0;
        int s3 = v3 ? ei[i3] : 0,   d3 = v3 ? ei[E + i3] : 0;
        int p0 = atomicAdd(&g_cnt[d0], 1);
        int p1 = v1 ? atomicAdd(&g_cnt[d1], 1) : 0;
        int p2 = v2 ? atomicAdd(&g_cnt[d2], 1) : 0;
        int p3 = v3 ? atomicAdd(&g_cnt[d3], 1) : 0;
        if (p0 < CAP)       g_csr_src[(d0 << 7) + p0] = s0;
        if (v1 && p1 < CAP) g_csr_src[(d1 << 7) + p1] = s1;
        if (v2 && p2 < CAP) g_csr_src[(d2 << 7) + p2] = s2;
        if (v3 && p3 < CAP) g_csr_src[(d3 << 7) + p3] = s3;
        return;
    }

    // ---- gemm1 body ----
    extern __shared__ __align__(16) char dynsmem[];
    __half* sxh = (__half*)dynsmem;                    // 128*XROW halves
    __half* sW1 = (__half*)(dynsmem + 128 * XROW * 2); // 128*128 halves

    int tid = threadIdx.x;
    int nbase = blockIdx.x * 128;

    const float4* x4 = (const float4*)x;
#pragma unroll
    for (int i = 0; i < 16; i++) {
        int f = tid + 256 * i;
        int row = f >> 5, kc = (f & 31) * 4;
        int n = nbase + row;
        float4 v = (n < N) ? x4[n * 32 + (f & 31)] : make_float4(0.f, 0.f, 0.f, 0.f);
        *(__half2*)&sxh[row * XROW + kc]     = __floats2half2_rn(v.x, v.y);
        *(__half2*)&sxh[row * XROW + kc + 2] = __floats2half2_rn(v.z, v.w);
    }
    {
        const uint2* src = (const uint2*)g_W1f;
        uint2* dst = (uint2*)sW1;
#pragma unroll
        for (int i = 0; i < 16; i++) dst[tid + 256 * i] = src[tid + 256 * i];
    }
    __syncthreads();

    int w = tid >> 5, lane = tid & 31;
    int mt16 = w * 16;
    int r = lane >> 2, cq = (lane & 3) * 2;

    float c[16][4];
#pragma unroll
    for (int nt = 0; nt < 16; nt++)
#pragma unroll
        for (int j = 0; j < 4; j++) c[nt][j] = 0.f;

    const uint2* W1f2 = (const uint2*)sW1;
#pragma unroll
    for (int ks = 0; ks < 8; ks++) {
        int k0 = ks * 16;
        unsigned a0 = *(const unsigned*)&sxh[(mt16 + r) * XROW + k0 + cq];
        unsigned a1 = *(const unsigned*)&sxh[(mt16 + r + 8) * XROW + k0 + cq];
        unsigned a2 = *(const unsigned*)&sxh[(mt16 + r) * XROW + k0 + cq + 8];
        unsigned a3 = *(const unsigned*)&sxh[(mt16 + r + 8) * XROW + k0 + cq + 8];
#pragma unroll
        for (int nt = 0; nt < 16; nt++) {
            uint2 b = W1f2[(ks * 16 + nt) * 32 + lane];
            asm volatile(
                "mma.sync.aligned.m16n8k16.row.col.f32.f16.f16.f32 "
                "{%0,%1,%2,%3}, {%4,%5,%6,%7}, {%8,%9}, {%0,%1,%2,%3};"
                : "+f"(c[nt][0]), "+f"(c[nt][1]), "+f"(c[nt][2]), "+f"(c[nt][3])
                : "r"(a0), "r"(a1), "r"(a2), "r"(a3), "r"(b.x), "r"(b.y));
        }
    }

    int node0 = nbase + mt16 + r;
    int node1 = node0 + 8;
    float p0 = 0.f, q0 = 0.f, p1 = 0.f, q1 = 0.f;
    __half2* h1v = (__half2*)g_h1h;
#pragma unroll
    for (int nt = 0; nt < 16; nt++) {
        int col = nt * 8 + cq;
        float as0 = a_src[col], as1 = a_src[col + 1];
        float ad0 = a_dst[col], ad1 = a_dst[col + 1];
        p0 += c[nt][0] * as0 + c[nt][1] * as1;
        q0 += c[nt][0] * ad0 + c[nt][1] * ad1;
        p1 += c[nt][2] * as0 + c[nt][3] * as1;
        q1 += c[nt][2] * ad0 + c[nt][3] * ad1;
        if (node0 < N) h1v[node0 * 64 + (col >> 1)] = __floats2half2_rn(c[nt][0], c[nt][1]);
        if (node1 < N) h1v[node1 * 64 + (col >> 1)] = __floats2half2_rn(c[nt][2], c[nt][3]);
    }
#pragma unroll
    for (int o = 1; o <= 2; o <<= 1) {
        p0 += __shfl_xor_sync(0xffffffffu, p0, o);
        q0 += __shfl_xor_sync(0xffffffffu, q0, o);
        p1 += __shfl_xor_sync(0xffffffffu, p1, o);
        q1 += __shfl_xor_sync(0xffffffffu, q1, o);
    }
    if ((lane & 3) == 0) {
        if (node0 < N) { g_s1s[node0] = p0; g_s1d[node0] = q0; }
        if (node1 < N) { g_s1s[node1] = p1; g_s1d[node1] = q1; }
    }
}

// Layer-1 aggregation: ONE WARP per node, smem-staged (offset, weight);
// self-loop term added analytically; fused relu(+b1)@W2 epilogue.
__global__ void k_agg1(const float* __restrict__ b1, const float* __restrict__ W2,
                       const float* __restrict__ as2, const float* __restrict__ ad2,
                       int N) {
    __shared__ uint2 sbuf[8][32];
    int wid = threadIdx.x >> 5;
    int lane = threadIdx.x & 31;
    int w = blockIdx.x * 8 + wid;
    if (w >= N) return;
    int base = w << 7;
    int cnt = g_cnt[w];
    float sd = g_s1d[w];

    float z = 0.f;
    float acc0 = 0.f, acc1 = 0.f, acc2 = 0.f, acc3 = 0.f;
    const uint2* h1v = (const uint2*)g_h1h;   // 32 x uint2 per row

    for (int c0 = 0; c0 < cnt; c0 += 32) {
        int p = c0 + lane;
        unsigned soff = 0;
        float ex = 0.f;
        if (p < cnt) {
            int s = g_csr_src[base + p];
            ex = __expf(lrelu(g_s1s[s] + sd));
            z += ex;
            soff = (unsigned)s * 32u;          // premultiplied uint2 row offset
        }
        sbuf[wid][lane] = make_uint2(soff, __float_as_uint(ex));
        __syncwarp();
        int m = min(32, cnt - c0);
#pragma unroll 8
        for (int j = 0; j < m; j++) {
            uint2 se = sbuf[wid][j];           // broadcast LDS.64
            float a = __uint_as_float(se.y);
            uint2 hv = __ldg(&h1v[se.x + lane]);
            float2 f01 = __half22float2(*(__half2*)&hv.x);
            float2 f23 = __half22float2(*(__half2*)&hv.y);
            acc0 = fmaf(a, f01.x, acc0);
            acc1 = fmaf(a, f01.y, acc1);
            acc2 = fmaf(a, f23.x, acc2);
            acc3 = fmaf(a, f23.y, acc3);
        }
        __syncwarp();
    }
#pragma unroll
    for (int o = 16; o > 0; o >>= 1) z += __shfl_xor_sync(0xffffffffu, z, o);

    // analytic self-loop term (same on all lanes post-reduce)
    float a_self = __expf(lrelu(g_s1s[w] + sd));
    z += a_self;
    {
        uint2 hv = h1v[(unsigned)w * 32u + lane];
        float2 f01 = __half22float2(*(__half2*)&hv.x);
        float2 f23 = __half22float2(*(__half2*)&hv.y);
        acc0 = fmaf(a_self, f01.x, acc0);
        acc1 = fmaf(a_self, f01.y, acc1);
        acc2 = fmaf(a_self, f23.x, acc2);
        acc3 = fmaf(a_self, f23.y, acc3);
    }

    // epilogue: features f = lane*4 + {0..3}
    float4 bv = ((const float4*)b1)[lane];
    float g0 = fmaxf(acc0 / z + bv.x, 0.f);
    float g1 = fmaxf(acc1 / z + bv.y, 0.f);
    float g2 = fmaxf(acc2 / z + bv.z, 0.f);
    float g3 = fmaxf(acc3 / z + bv.w, 0.f);
    const float4* W24 = (const float4*)W2;
    float4 wA = W24[lane * 2 + 0];
    float4 wB = W24[lane * 2 + 1];
    float h0 = g0 * wA.x + g1 * wA.z + g2 * wB.x + g3 * wB.z;
    float h1 = g0 * wA.y + g1 * wA.w + g2 * wB.y + g3 * wB.w;
#pragma unroll
    for (int o = 16; o > 0; o >>= 1) {
        h0 += __shfl_down_sync(0xffffffffu, h0, o);
        h1 += __shfl_down_sync(0xffffffffu, h1, o);
    }
    if (lane == 0) {
        g_n2[w] = make_float4(h0, h1,
                              h0 * as2[0] + h1 * as2[1],
                              h0 * ad2[0] + h1 * ad2[1]);
    }
}

// Layer-2: EIGHT lanes per node, 2-way prefetch for MLP; analytic self term.
__global__ void k_agg2(const float* __restrict__ b2, float* __restrict__ out, int N) {
    int g = (blockIdx.x * blockDim.x + threadIdx.x) >> 3;   // global 8-lane group
    int li = threadIdx.x & 7;
    if (g >= N) return;
    int base = g << 7;
    int cnt = g_cnt[g];
    float4 vs = g_n2[g];
    float sd = vs.w;

    float z = 0.f, acc0 = 0.f, acc1 = 0.f;
    for (int p = li; p < cnt; p += 16) {
        int s0 = g_csr_src[base + p];
        int p1 = p + 8;
        bool bb = p1 < cnt;
        int s1 = bb ? g_csr_src[base + p1] : 0;
        float4 v0 = g_n2[s0];
        float4 v1 = bb ? g_n2[s1] : make_float4(0.f, 0.f, 0.f, 0.f);
        float e0 = __expf(lrelu(v0.z + sd));
        z += e0;
        acc0 = fmaf(e0, v0.x, acc0);
        acc1 = fmaf(e0, v0.y, acc1);
        if (bb) {
            float e1 = __expf(lrelu(v1.z + sd));
            z += e1;
            acc0 = fmaf(e1, v1.x, acc0);
            acc1 = fmaf(e1, v1.y, acc1);
        }
    }
#pragma unroll
    for (int o = 4; o > 0; o >>= 1) {
        z    += __shfl_xor_sync(0xffffffffu, z, o);
        acc0 += __shfl_xor_sync(0xffffffffu, acc0, o);
        acc1 += __shfl_xor_sync(0xffffffffu, acc1, o);
    }
    if (li == 0) {
        float es = __expf(lrelu(vs.z + sd));   // self-loop
        z += es;
        acc0 = fmaf(es, vs.x, acc0);
        acc1 = fmaf(es, vs.y, acc1);
        out[g * 2 + 0] = acc0 / z + b2[0];
        out[g * 2 + 1] = acc1 / z + b2[1];
    }
}

// ---------------- launch ----------------
extern "C" void kernel_launch(void* const* d_in, const int* in_sizes, int n_in,
                              void* d_out, int out_size) {
    const float* x      = (const float*)d_in[0];
    const int*   ei     = (const int*)d_in[1];
    const float* W1     = (const float*)d_in[2];
    const float* a_src1 = (const float*)d_in[3];
    const float* a_dst1 = (const float*)d_in[4];
    const float* b1     = (const float*)d_in[5];
    const float* W2     = (const float*)d_in[6];
    const float* a_src2 = (const float*)d_in[7];
    const float* a_dst2 = (const float*)d_in[8];
    const float* b2     = (const float*)d_in[9];
    float*       out    = (float*)d_out;

    int N = in_sizes[0] / F1;
    int E = in_sizes[1] / 2;
    int G = (N + 127) / 128;                       // gemm1 blocks
    int F = ((E + 3) / 4 + 255) / 256;             // fill blocks

    cudaFuncSetAttribute(k_phase1, cudaFuncAttributeMaxDynamicSharedMemorySize,
                         GEMM1_SMEM);

    k_init<<<256, 256>>>(W1, N);
    k_phase1<<<G + F, 256, GEMM1_SMEM>>>(x, a_src1, a_dst1, ei, N, E, G);
    k_agg1<<<(N + 7) / 8, 256>>>(b1, W2, a_src2, a_dst2, N);
    k_agg2<<<(N * 8 + 255) / 256, 256>>>(b2, out, N);
}